// round 1
// baseline (speedup 1.0000x reference)
#include <cuda_runtime.h>
#include <cstdint>

// Problem constants
#define NB 4
#define NC 256
#define NHW 4096
#define NCP 64

// Scratch (device globals; no allocation allowed)
__device__ float g_CM[27][256][64];        // combined red matrices, TRANSPOSED: [combo][c_in][cp]
__device__ float g_pp_sum[27][4][4][64];   // per-chunk partial pooling sums   [combo][b][chunk][cp]
__device__ float g_pp_max[27][4][4][64];   // per-chunk partial pooling maxes
__device__ float g_o[9][4][256];           // sigmoid gate per combo e

// ---- f32x2 helpers (FFMA2 only reachable via PTX) ----
static __device__ __forceinline__ unsigned long long pk2(float x, float y) {
    unsigned long long r;
    asm("mov.b64 %0, {%1,%2};" : "=l"(r) : "f"(x), "f"(y));
    return r;
}
static __device__ __forceinline__ void upk2(unsigned long long v, float& x, float& y) {
    asm("mov.b64 {%0,%1}, %2;" : "=f"(x), "=f"(y) : "l"(v));
}
static __device__ __forceinline__ unsigned long long ffma2(
    unsigned long long a, unsigned long long b, unsigned long long c) {
    unsigned long long d;
    asm("fma.rn.f32x2 %0, %1, %2, %3;" : "=l"(d) : "l"(a), "l"(b), "l"(c));
    return d;
}

// ============================================================================
// K1: combined matrices  M[combo][cp][cin] = sum_k Wred[e][cp][k] * Wqkv[w][k][cin]
//     stored transposed into g_CM[combo][cin][cp].
//     grid (27, 4 cin-tiles), block 256 (16x16, 4x4 micro-tile)
// ============================================================================
__global__ void k1_cm(const float* __restrict__ Wqkv, const float* __restrict__ Wred) {
    int combo = blockIdx.x;
    int e = combo / 3, r = combo % 3;
    int ii = e / 3, jj = e % 3;
    int w = (r == 0) ? 3 * jj : (r == 1) ? (3 * ii + 1) : (3 * jj + 2);
    int cc0 = blockIdx.y * 64;

    __shared__ float sA[64][65];  // Wred[e][cp][k-chunk]
    __shared__ float sB[64][65];  // Wqkv[w][k-chunk][cin-tile]

    int tx = threadIdx.x & 15, ty = threadIdx.x >> 4;
    float acc[4][4] = {};

    const float* A = Wred + (size_t)e * 64 * 256;
    const float* Bm = Wqkv + (size_t)w * 65536;

    for (int k0 = 0; k0 < 256; k0 += 64) {
        for (int idx = threadIdx.x; idx < 4096; idx += 256) {
            int rr = idx >> 6, cl = idx & 63;
            sA[rr][cl] = A[rr * 256 + k0 + cl];
            sB[rr][cl] = Bm[(k0 + rr) * 256 + cc0 + cl];
        }
        __syncthreads();
#pragma unroll
        for (int kk = 0; kk < 64; kk++) {
            float av[4], bv[4];
#pragma unroll
            for (int u = 0; u < 4; u++) av[u] = sA[ty * 4 + u][kk];
#pragma unroll
            for (int v = 0; v < 4; v++) bv[v] = sB[kk][tx * 4 + v];
#pragma unroll
            for (int u = 0; u < 4; u++)
#pragma unroll
                for (int v = 0; v < 4; v++) acc[u][v] = fmaf(av[u], bv[v], acc[u][v]);
        }
        __syncthreads();
    }
#pragma unroll
    for (int u = 0; u < 4; u++)
#pragma unroll
        for (int v = 0; v < 4; v++)
            g_CM[combo][cc0 + tx * 4 + v][ty * 4 + u] = acc[u][v];
}

// ============================================================================
// K2: fused reduced projection + relu + (sum,max) pooling.
//     For combo (e,r): pool( relu( M[combo] @ x_src[b] ) ) over HW.
//     grid (27, 4 batch, 4 hw-chunks of 1024), block 256.
//     Thread: 32 cp (16 f32x2 pairs) x 2 hw columns. FFMA2 inner loop.
// ============================================================================
__global__ void __launch_bounds__(256, 1)
k2_pool(const float* __restrict__ xt, const float* __restrict__ xb, const float* __restrict__ xm) {
    extern __shared__ float sw[];  // 256*64 floats: M transposed [cin][cp]
    int combo = blockIdx.x;
    int e = combo / 3, r = combo % 3;
    int ii = e / 3, jj = e % 3;
    int src = (r == 1) ? ii : jj;
    const float* xs = (src == 0) ? xt : (src == 1) ? xb : xm;
    int bidx = blockIdx.y;
    int chunk = blockIdx.z;

    // load combined matrix (already transposed in global) — coalesced, conflict-free
    {
        const float* gsrc = &g_CM[combo][0][0];
        for (int idx = threadIdx.x; idx < 64 * 256; idx += 256) sw[idx] = gsrc[idx];
    }
    __syncthreads();

    int half = threadIdx.x >> 7;        // cp half: 0 or 1
    int pair = threadIdx.x & 127;       // hw float2-pair index within subtile
    int cp0 = half * 32;

    const float2* X2 = (const float2*)(xs + (size_t)bidx * NC * NHW);
    const unsigned long long* swu = (const unsigned long long*)sw;

    float sumv[32], maxv[32];
#pragma unroll
    for (int k = 0; k < 32; k++) { sumv[k] = 0.f; maxv[k] = 0.f; }

    for (int st = 0; st < 4; st++) {
        int pcol = chunk * 512 + st * 128 + pair;  // float2 column index
        unsigned long long acc0[16], acc1[16];
#pragma unroll
        for (int k = 0; k < 16; k++) { acc0[k] = 0ull; acc1[k] = 0ull; }

        const float2* xp = X2 + pcol;
#pragma unroll 2
        for (int c = 0; c < 256; c++) {
            float2 x = xp[c * (NHW / 2)];
            unsigned long long xx0 = pk2(x.x, x.x);
            unsigned long long xx1 = pk2(x.y, x.y);
            int wbase = (c * 64 + cp0) >> 1;  // ull units
#pragma unroll
            for (int k = 0; k < 16; k++) {
                unsigned long long wv = swu[wbase + k];
                acc0[k] = ffma2(wv, xx0, acc0[k]);
                acc1[k] = ffma2(wv, xx1, acc1[k]);
            }
        }
        // relu + pool update
#pragma unroll
        for (int k = 0; k < 16; k++) {
            float a, b2, c1, d1;
            upk2(acc0[k], a, b2);   // a: cp0+2k col0, b2: cp0+2k+1 col0
            upk2(acc1[k], c1, d1);  // c1: cp0+2k col1, d1: cp0+2k+1 col1
            float r0 = fmaxf(a, 0.f), r1 = fmaxf(b2, 0.f);
            float r2 = fmaxf(c1, 0.f), r3 = fmaxf(d1, 0.f);
            sumv[2 * k]     += r0 + r2;
            sumv[2 * k + 1] += r1 + r3;
            maxv[2 * k]     = fmaxf(maxv[2 * k], fmaxf(r0, r2));
            maxv[2 * k + 1] = fmaxf(maxv[2 * k + 1], fmaxf(r1, r3));
        }
    }

    // block reduction over the 128 hw-pair threads per cp (reuse smem: 64KB exactly)
    __syncthreads();
    float* ssum = sw;                  // [64][128]
    float* smax = sw + 64 * 128;       // [64][128]
#pragma unroll
    for (int k = 0; k < 32; k++) {
        ssum[(cp0 + k) * 128 + pair] = sumv[k];
        smax[(cp0 + k) * 128 + pair] = maxv[k];
    }
    __syncthreads();
    if (threadIdx.x < 64) {
        float s = 0.f, mx = 0.f;
        const float* ps = ssum + threadIdx.x * 128;
        const float* pm = smax + threadIdx.x * 128;
        for (int i2 = 0; i2 < 128; i2++) {
            s += ps[i2];
            mx = fmaxf(mx, pm[i2]);
        }
        g_pp_sum[combo][bidx][chunk][threadIdx.x] = s;
        g_pp_max[combo][bidx][chunk][threadIdx.x] = mx;
    }
}

// ============================================================================
// K3: tiny channel-attention math per (e, b): softmax + vout + sigmoid gate.
//     grid (9, 4), block 64.
// ============================================================================
__global__ void k3_attn(const float* __restrict__ Wrec) {
    int e = blockIdx.x, bidx = blockIdx.y;
    __shared__ float fS[64], gS[64], hS[64], vout[64];
    int j = threadIdx.x;

    // finalize pools: mean + max over HW (reduce the 4 hw-chunk partials)
    {
        float fs = 0.f, fm = 0.f, gs = 0.f, gm = 0.f, hs = 0.f, hm = 0.f;
#pragma unroll
        for (int ch = 0; ch < 4; ch++) {
            fs += g_pp_sum[e * 3 + 1][bidx][ch][j];  fm = fmaxf(fm, g_pp_max[e * 3 + 1][bidx][ch][j]);  // f = pool(kr)
            gs += g_pp_sum[e * 3 + 0][bidx][ch][j];  gm = fmaxf(gm, g_pp_max[e * 3 + 0][bidx][ch][j]);  // g = pool(qr)
            hs += g_pp_sum[e * 3 + 2][bidx][ch][j];  hm = fmaxf(hm, g_pp_max[e * 3 + 2][bidx][ch][j]);  // h = pool(vr)
        }
        const float inv = 1.f / 4096.f;
        fS[j] = fs * inv + fm;
        gS[j] = gs * inv + gm;
        hS[j] = hs * inv + hm;
    }
    __syncthreads();

    // softmax over i of s[i][j] = f[i]*g[j];  vout[j] = sum_i h[i]*beta[i][j]
    float gj = gS[j];
    float mx = -1e30f;
#pragma unroll 8
    for (int i = 0; i < 64; i++) mx = fmaxf(mx, fS[i] * gj);
    float den = 0.f, num = 0.f;
#pragma unroll 8
    for (int i = 0; i < 64; i++) {
        float ev = expf(fS[i] * gj - mx);
        den += ev;
        num += hS[i] * ev;
    }
    vout[j] = num / den;
    __syncthreads();

    // o[b][c] = sigmoid( sum_j vout[j] * Wrec[e][c][j] )
    for (int c = j; c < 256; c += 64) {
        const float* wr = Wrec + ((size_t)e * 256 + c) * 64;
        float acc = 0.f;
#pragma unroll 8
        for (int q = 0; q < 64; q++) acc = fmaf(vout[q], wr[q], acc);
        g_o[e][bidx][c] = 1.f / (1.f + expf(-acc));
    }
}

// ============================================================================
// K5: output GEMM. out[b][c][hw] = sum_s Meff[b][s][c][:] @ x_s[b][:][hw]
//     Meff built on the fly in smem from W_qkv and the gate coefficients.
//     grid (4 c-tiles, 4 b, 16 hw-tiles of 256), block 256.
// ============================================================================
__global__ void __launch_bounds__(256, 1)
k5_out(const float* __restrict__ xt, const float* __restrict__ xb, const float* __restrict__ xm,
       const float* __restrict__ Wqkv, float* __restrict__ out) {
    extern __shared__ float sw[];  // [cc=256][lc=64] transposed Meff tile
    __shared__ float sAc[64], sBc[64];

    int ct = blockIdx.x, bidx = blockIdx.y, hz = blockIdx.z;
    int half = threadIdx.x >> 7;
    int pair = threadIdx.x & 127;
    int c0 = half * 32;

    unsigned long long acc0[16], acc1[16];
#pragma unroll
    for (int k = 0; k < 16; k++) { acc0[k] = 0ull; acc1[k] = 0ull; }

    const unsigned long long* swu = (const unsigned long long*)sw;

    for (int s = 0; s < 3; s++) {
        __syncthreads();  // protect smem reuse across s iterations
        // gate coefficients for this c-tile
        if (threadIdx.x < 64) {
            int c = ct * 64 + threadIdx.x;
            sAc[threadIdx.x] = g_o[s][bidx][c] + g_o[s + 3][bidx][c] + g_o[s + 6][bidx][c];
            sBc[threadIdx.x] = g_o[3 * s][bidx][c] + g_o[3 * s + 1][bidx][c] + g_o[3 * s + 2][bidx][c];
        }
        __syncthreads();
        // build Meff tile (transposed [cc][lc]); coalesced global reads
        const float* Wq = Wqkv + (size_t)(3 * s) * 65536 + (size_t)ct * 64 * 256;
        const float* Wk = Wq + 65536;
        const float* Wv = Wk + 65536;
        for (int idx = threadIdx.x; idx < 64 * 256; idx += 256) {
            int lc = idx >> 8;       // local output channel
            int cc = idx & 255;      // input channel
            float wq = Wq[lc * 256 + cc];
            float wk = Wk[lc * 256 + cc];
            float wv = Wv[lc * 256 + cc];
            sw[cc * 64 + lc] = sAc[lc] * (wq + wv) + sBc[lc] * wk;
        }
        __syncthreads();

        const float* xs = (s == 0) ? xt : (s == 1) ? xb : xm;
        const float2* X2 = (const float2*)(xs + (size_t)bidx * NC * NHW);
        const float2* xp = X2 + hz * 128 + pair;
#pragma unroll 2
        for (int cc = 0; cc < 256; cc++) {
            float2 x = xp[cc * (NHW / 2)];
            unsigned long long xx0 = pk2(x.x, x.x);
            unsigned long long xx1 = pk2(x.y, x.y);
            int wbase = (cc * 64 + c0) >> 1;
#pragma unroll
            for (int k = 0; k < 16; k++) {
                unsigned long long wv2 = swu[wbase + k];
                acc0[k] = ffma2(wv2, xx0, acc0[k]);
                acc1[k] = ffma2(wv2, xx1, acc1[k]);
            }
        }
    }

    // write out (coalesced float2 stores)
    float2* out2 = (float2*)out;
#pragma unroll
    for (int k = 0; k < 16; k++) {
        float a, b2, c1, d1;
        upk2(acc0[k], a, b2);
        upk2(acc1[k], c1, d1);
        int c = ct * 64 + c0 + 2 * k;
        size_t idx = ((size_t)bidx * NC + c) * (NHW / 2) + hz * 128 + pair;
        out2[idx] = make_float2(a, c1);
        out2[idx + (NHW / 2)] = make_float2(b2, d1);
    }
}

// ============================================================================
extern "C" void kernel_launch(void* const* d_in, const int* in_sizes, int n_in,
                              void* d_out, int out_size) {
    (void)in_sizes; (void)n_in; (void)out_size;
    const float* t    = (const float*)d_in[0];
    const float* bb   = (const float*)d_in[1];
    const float* mm   = (const float*)d_in[2];
    const float* Wqkv = (const float*)d_in[3];
    const float* Wred = (const float*)d_in[4];
    const float* Wrec = (const float*)d_in[5];
    float* out = (float*)d_out;

    cudaFuncSetAttribute(k2_pool, cudaFuncAttributeMaxDynamicSharedMemorySize, 65536);
    cudaFuncSetAttribute(k5_out, cudaFuncAttributeMaxDynamicSharedMemorySize, 65536);

    k1_cm<<<dim3(27, 4), 256>>>(Wqkv, Wred);
    k2_pool<<<dim3(27, 4, 4), 256, 65536>>>(t, bb, mm);
    k3_attn<<<dim3(9, 4), 64>>>(Wrec);
    k5_out<<<dim3(4, 4, 16), 256, 65536>>>(t, bb, mm, Wqkv, out);
}

// round 2
// speedup vs baseline: 1.2790x; 1.2790x over previous
#include <cuda_runtime.h>
#include <cstdint>

#define NB 4
#define NC 256
#define NHW 4096
#define NCP 64

__device__ float g_CM[27][256][64];        // combined red matrices, TRANSPOSED: [combo][c_in][cp]
__device__ float g_pp_sum[27][4][4][64];   // [combo][b][chunk][cp]
__device__ float g_pp_max[27][4][4][64];
__device__ float g_o[9][4][256];           // sigmoid gate per combo e

// ---- f32x2 helpers ----
static __device__ __forceinline__ unsigned long long pk2(float x, float y) {
    unsigned long long r;
    asm("mov.b64 %0, {%1,%2};" : "=l"(r) : "f"(x), "f"(y));
    return r;
}
static __device__ __forceinline__ void upk2(unsigned long long v, float& x, float& y) {
    asm("mov.b64 {%0,%1}, %2;" : "=f"(x), "=f"(y) : "l"(v));
}
static __device__ __forceinline__ unsigned long long ffma2(
    unsigned long long a, unsigned long long b, unsigned long long c) {
    unsigned long long d;
    asm("fma.rn.f32x2 %0, %1, %2, %3;" : "=l"(d) : "l"(a), "l"(b), "l"(c));
    return d;
}

// ============================================================================
// K1: combined matrices  g_CM[combo][cin][cp] = (Wred[e] @ Wqkv[w])^T
// ============================================================================
__global__ void k1_cm(const float* __restrict__ Wqkv, const float* __restrict__ Wred) {
    int combo = blockIdx.x;
    int e = combo / 3, r = combo % 3;
    int ii = e / 3, jj = e % 3;
    int w = (r == 0) ? 3 * jj : (r == 1) ? (3 * ii + 1) : (3 * jj + 2);
    int cc0 = blockIdx.y * 64;

    __shared__ float sA[64][65];
    __shared__ float sB[64][65];

    int tx = threadIdx.x & 15, ty = threadIdx.x >> 4;
    float acc[4][4] = {};

    const float* A = Wred + (size_t)e * 64 * 256;
    const float* Bm = Wqkv + (size_t)w * 65536;

    for (int k0 = 0; k0 < 256; k0 += 64) {
        for (int idx = threadIdx.x; idx < 4096; idx += 256) {
            int rr = idx >> 6, cl = idx & 63;
            sA[rr][cl] = A[rr * 256 + k0 + cl];
            sB[rr][cl] = Bm[(k0 + rr) * 256 + cc0 + cl];
        }
        __syncthreads();
#pragma unroll
        for (int kk = 0; kk < 64; kk++) {
            float av[4], bv[4];
#pragma unroll
            for (int u = 0; u < 4; u++) av[u] = sA[ty * 4 + u][kk];
#pragma unroll
            for (int v = 0; v < 4; v++) bv[v] = sB[kk][tx * 4 + v];
#pragma unroll
            for (int u = 0; u < 4; u++)
#pragma unroll
                for (int v = 0; v < 4; v++) acc[u][v] = fmaf(av[u], bv[v], acc[u][v]);
        }
        __syncthreads();
    }
#pragma unroll
    for (int u = 0; u < 4; u++)
#pragma unroll
        for (int v = 0; v < 4; v++)
            g_CM[combo][cc0 + tx * 4 + v][ty * 4 + u] = acc[u][v];
}

// ============================================================================
// K2: fused reduced projection + relu + (sum,max) pooling.
//     grid (27, 4 batch, 4 hw-chunks of 1024), block 512 (16 warps).
//     Thread: 16 cp (8 f32x2 pairs) x 1 float2 (2 hw cols). PF=4 x-prefetch.
// ============================================================================
__global__ void __launch_bounds__(512, 1)
k2_pool(const float* __restrict__ xt, const float* __restrict__ xb, const float* __restrict__ xm) {
    extern __shared__ float sw[];  // 64KB: weights [cin=256][cp=64]
    int combo = blockIdx.x;
    int e = combo / 3, r = combo % 3;
    int ii = e / 3, jj = e % 3;
    int src = (r == 1) ? ii : jj;
    const float* xs = (src == 0) ? xt : (src == 1) ? xb : xm;
    int bidx = blockIdx.y;
    int chunk = blockIdx.z;

    {
        const float* gsrc = &g_CM[combo][0][0];
        for (int idx = threadIdx.x; idx < 64 * 256; idx += 512) sw[idx] = gsrc[idx];
    }
    __syncthreads();

    int q    = threadIdx.x >> 7;    // cp quarter 0..3
    int pair = threadIdx.x & 127;   // hw float2 index
    int cp0  = q * 16;

    const float2* X2 = (const float2*)(xs + (size_t)bidx * NC * NHW);
    const unsigned long long* swu = (const unsigned long long*)sw;

    float sumv[16], maxv[16];
#pragma unroll
    for (int k = 0; k < 16; k++) { sumv[k] = 0.f; maxv[k] = 0.f; }

    for (int st = 0; st < 4; st++) {
        int pcol = chunk * 512 + st * 128 + pair;
        const float2* xp = X2 + pcol;

        unsigned long long accA[8], accB[8];
#pragma unroll
        for (int k = 0; k < 8; k++) { accA[k] = 0ull; accB[k] = 0ull; }

        float2 xq[4];
#pragma unroll
        for (int p = 0; p < 4; p++) xq[p] = xp[p * (NHW / 2)];

        for (int c0 = 0; c0 < 252; c0 += 4) {
#pragma unroll
            for (int u = 0; u < 4; u++) {
                float2 x = xq[u];
                xq[u] = xp[(c0 + u + 4) * (NHW / 2)];
                unsigned long long xx0 = pk2(x.x, x.x);
                unsigned long long xx1 = pk2(x.y, x.y);
                int wb = ((c0 + u) * 64 + cp0) >> 1;
#pragma unroll
                for (int k = 0; k < 8; k++) {
                    unsigned long long wv = swu[wb + k];
                    accA[k] = ffma2(wv, xx0, accA[k]);
                    accB[k] = ffma2(wv, xx1, accB[k]);
                }
            }
        }
#pragma unroll
        for (int u = 0; u < 4; u++) {
            float2 x = xq[u];
            unsigned long long xx0 = pk2(x.x, x.x);
            unsigned long long xx1 = pk2(x.y, x.y);
            int wb = ((252 + u) * 64 + cp0) >> 1;
#pragma unroll
            for (int k = 0; k < 8; k++) {
                unsigned long long wv = swu[wb + k];
                accA[k] = ffma2(wv, xx0, accA[k]);
                accB[k] = ffma2(wv, xx1, accB[k]);
            }
        }
        // relu + pool update
#pragma unroll
        for (int k = 0; k < 8; k++) {
            float a, b2, c1, d1;
            upk2(accA[k], a, b2);
            upk2(accB[k], c1, d1);
            float r0 = fmaxf(a, 0.f), r1 = fmaxf(b2, 0.f);
            float r2 = fmaxf(c1, 0.f), r3 = fmaxf(d1, 0.f);
            sumv[2 * k]     += r0 + r2;
            sumv[2 * k + 1] += r1 + r3;
            maxv[2 * k]     = fmaxf(maxv[2 * k], fmaxf(r0, r2));
            maxv[2 * k + 1] = fmaxf(maxv[2 * k + 1], fmaxf(r1, r3));
        }
    }

    // block reduction over 128 pairs (reuse smem: 2 x 32KB = 64KB)
    __syncthreads();
    float* ssum = sw;                  // [64][128]
    float* smax = sw + 64 * 128;
#pragma unroll
    for (int k = 0; k < 16; k++) {
        ssum[(cp0 + k) * 128 + pair] = sumv[k];
        smax[(cp0 + k) * 128 + pair] = maxv[k];
    }
    __syncthreads();
    if (threadIdx.x < 64) {
        float s = 0.f, mx = 0.f;
        const float* ps = ssum + threadIdx.x * 128;
        const float* pm = smax + threadIdx.x * 128;
#pragma unroll 8
        for (int i2 = 0; i2 < 128; i2++) {
            s += ps[i2];
            mx = fmaxf(mx, pm[i2]);
        }
        g_pp_sum[combo][bidx][chunk][threadIdx.x] = s;
        g_pp_max[combo][bidx][chunk][threadIdx.x] = mx;
    }
}

// ============================================================================
// K3: tiny channel-attention math per (e, b). grid (9,4), block 64.
// ============================================================================
__global__ void k3_attn(const float* __restrict__ Wrec) {
    int e = blockIdx.x, bidx = blockIdx.y;
    __shared__ float fS[64], gS[64], hS[64], vout[64];
    int j = threadIdx.x;

    {
        float fs = 0.f, fm = 0.f, gs = 0.f, gm = 0.f, hs = 0.f, hm = 0.f;
#pragma unroll
        for (int ch = 0; ch < 4; ch++) {
            fs += g_pp_sum[e * 3 + 1][bidx][ch][j];  fm = fmaxf(fm, g_pp_max[e * 3 + 1][bidx][ch][j]);
            gs += g_pp_sum[e * 3 + 0][bidx][ch][j];  gm = fmaxf(gm, g_pp_max[e * 3 + 0][bidx][ch][j]);
            hs += g_pp_sum[e * 3 + 2][bidx][ch][j];  hm = fmaxf(hm, g_pp_max[e * 3 + 2][bidx][ch][j]);
        }
        const float inv = 1.f / 4096.f;
        fS[j] = fs * inv + fm;
        gS[j] = gs * inv + gm;
        hS[j] = hs * inv + hm;
    }
    __syncthreads();

    float gj = gS[j];
    float mx = -1e30f;
#pragma unroll 8
    for (int i = 0; i < 64; i++) mx = fmaxf(mx, fS[i] * gj);
    float den = 0.f, num = 0.f;
#pragma unroll 8
    for (int i = 0; i < 64; i++) {
        float ev = expf(fS[i] * gj - mx);
        den += ev;
        num += hS[i] * ev;
    }
    vout[j] = num / den;
    __syncthreads();

    for (int c = j; c < 256; c += 64) {
        const float* wr = Wrec + ((size_t)e * 256 + c) * 64;
        float acc = 0.f;
#pragma unroll 8
        for (int qq = 0; qq < 64; qq++) acc = fmaf(vout[qq], wr[qq], acc);
        g_o[e][bidx][c] = 1.f / (1.f + expf(-acc));
    }
}

// ============================================================================
// K5: output GEMM with on-the-fly gated weight tile.
//     grid (4 c-tiles, 4 b, 16 hw-tiles of 256), block 512 (16 warps).
//     Thread: 16 lc x 1 float2; PF=4 x-prefetch; accumulate across 3 sources.
// ============================================================================
__global__ void __launch_bounds__(512, 1)
k5_out(const float* __restrict__ xt, const float* __restrict__ xb, const float* __restrict__ xm,
       const float* __restrict__ Wqkv, float* __restrict__ out) {
    extern __shared__ float sw[];  // [cc=256][lc=64] transposed Meff tile
    __shared__ float sAc[64], sBc[64];

    int ct = blockIdx.x, bidx = blockIdx.y, hz = blockIdx.z;
    int q    = threadIdx.x >> 7;
    int pair = threadIdx.x & 127;
    int c0r  = q * 16;   // local-channel offset within the 64-channel tile

    unsigned long long accA[8], accB[8];
#pragma unroll
    for (int k = 0; k < 8; k++) { accA[k] = 0ull; accB[k] = 0ull; }

    const unsigned long long* swu = (const unsigned long long*)sw;

    for (int s = 0; s < 3; s++) {
        __syncthreads();
        if (threadIdx.x < 64) {
            int c = ct * 64 + threadIdx.x;
            sAc[threadIdx.x] = g_o[s][bidx][c] + g_o[s + 3][bidx][c] + g_o[s + 6][bidx][c];
            sBc[threadIdx.x] = g_o[3 * s][bidx][c] + g_o[3 * s + 1][bidx][c] + g_o[3 * s + 2][bidx][c];
        }
        __syncthreads();
        const float* Wq = Wqkv + (size_t)(3 * s) * 65536 + (size_t)ct * 64 * 256;
        const float* Wk = Wq + 65536;
        const float* Wv = Wk + 65536;
        for (int idx = threadIdx.x; idx < 64 * 256; idx += 512) {
            int lc = idx >> 8;
            int cc = idx & 255;
            float wq = Wq[lc * 256 + cc];
            float wk = Wk[lc * 256 + cc];
            float wv = Wv[lc * 256 + cc];
            sw[cc * 64 + lc] = sAc[lc] * (wq + wv) + sBc[lc] * wk;
        }
        __syncthreads();

        const float* xs = (s == 0) ? xt : (s == 1) ? xb : xm;
        const float2* X2 = (const float2*)(xs + (size_t)bidx * NC * NHW);
        const float2* xp = X2 + hz * 128 + pair;

        float2 xq[4];
#pragma unroll
        for (int p = 0; p < 4; p++) xq[p] = xp[p * (NHW / 2)];

        for (int cc0 = 0; cc0 < 252; cc0 += 4) {
#pragma unroll
            for (int u = 0; u < 4; u++) {
                float2 x = xq[u];
                xq[u] = xp[(cc0 + u + 4) * (NHW / 2)];
                unsigned long long xx0 = pk2(x.x, x.x);
                unsigned long long xx1 = pk2(x.y, x.y);
                int wb = ((cc0 + u) * 64 + c0r) >> 1;
#pragma unroll
                for (int k = 0; k < 8; k++) {
                    unsigned long long wv2 = swu[wb + k];
                    accA[k] = ffma2(wv2, xx0, accA[k]);
                    accB[k] = ffma2(wv2, xx1, accB[k]);
                }
            }
        }
#pragma unroll
        for (int u = 0; u < 4; u++) {
            float2 x = xq[u];
            unsigned long long xx0 = pk2(x.x, x.x);
            unsigned long long xx1 = pk2(x.y, x.y);
            int wb = ((252 + u) * 64 + c0r) >> 1;
#pragma unroll
            for (int k = 0; k < 8; k++) {
                unsigned long long wv2 = swu[wb + k];
                accA[k] = ffma2(wv2, xx0, accA[k]);
                accB[k] = ffma2(wv2, xx1, accB[k]);
            }
        }
    }

    // write out: accA holds (lc, lc+1) for hw col0; accB for hw col1
    float2* out2 = (float2*)out;
#pragma unroll
    for (int k = 0; k < 8; k++) {
        float a, b2, c1, d1;
        upk2(accA[k], a, b2);
        upk2(accB[k], c1, d1);
        int c = ct * 64 + c0r + 2 * k;
        size_t idx = ((size_t)bidx * NC + c) * (NHW / 2) + hz * 128 + pair;
        out2[idx]             = make_float2(a, c1);
        out2[idx + (NHW / 2)] = make_float2(b2, d1);
    }
}

// ============================================================================
extern "C" void kernel_launch(void* const* d_in, const int* in_sizes, int n_in,
                              void* d_out, int out_size) {
    (void)in_sizes; (void)n_in; (void)out_size;
    const float* t    = (const float*)d_in[0];
    const float* bb   = (const float*)d_in[1];
    const float* mm   = (const float*)d_in[2];
    const float* Wqkv = (const float*)d_in[3];
    const float* Wred = (const float*)d_in[4];
    const float* Wrec = (const float*)d_in[5];
    float* out = (float*)d_out;

    cudaFuncSetAttribute(k2_pool, cudaFuncAttributeMaxDynamicSharedMemorySize, 65536);
    cudaFuncSetAttribute(k5_out, cudaFuncAttributeMaxDynamicSharedMemorySize, 65536);

    k1_cm<<<dim3(27, 4), 256>>>(Wqkv, Wred);
    k2_pool<<<dim3(27, 4, 4), 512, 65536>>>(t, bb, mm);
    k3_attn<<<dim3(9, 4), 64>>>(Wrec);
    k5_out<<<dim3(4, 4, 16), 512, 65536>>>(t, bb, mm, Wqkv, out);
}

// round 3
// speedup vs baseline: 1.4124x; 1.1043x over previous
#include <cuda_runtime.h>
#include <cstdint>

#define NB 4
#define NC 256
#define NHW 4096
#define NHW4 1024
#define NCP 64
#define CHK 16
typedef unsigned long long ull;

// Scratch (device globals)
__device__ __align__(16) float2 g_CMd[27][256][64];   // duplicated combined matrices [combo][cin][cp] = (w,w)
__device__ float g_pp_sum[27][4][8][64];
__device__ float g_pp_max[27][4][8][64];
__device__ float g_o[9][4][256];

// ---- f32x2 helpers ----
static __device__ __forceinline__ ull pk2(float x, float y) {
    ull r;
    asm("mov.b64 %0, {%1,%2};" : "=l"(r) : "f"(x), "f"(y));
    return r;
}
static __device__ __forceinline__ void upk2(ull v, float& x, float& y) {
    asm("mov.b64 {%0,%1}, %2;" : "=f"(x), "=f"(y) : "l"(v));
}
static __device__ __forceinline__ ull ffma2(ull a, ull b, ull c) {
    ull d;
    asm("fma.rn.f32x2 %0, %1, %2, %3;" : "=l"(d) : "l"(a), "l"(b), "l"(c));
    return d;
}
static __device__ __forceinline__ unsigned smem_u32(const void* p) {
    return (unsigned)__cvta_generic_to_shared(p);
}
static __device__ __forceinline__ void cp_async16(unsigned dst, const void* src) {
    asm volatile("cp.async.cg.shared.global [%0], [%1], 16;" :: "r"(dst), "l"(src));
}
#define CP_COMMIT() asm volatile("cp.async.commit_group;" ::: "memory")
#define CP_WAIT1()  asm volatile("cp.async.wait_group 1;" ::: "memory")
#define CP_WAIT0()  asm volatile("cp.async.wait_group 0;" ::: "memory")

// ============================================================================
// K1: combined matrices, duplicated store: g_CMd[combo][cin][cp] = (M^T, M^T)
// ============================================================================
__global__ void k1_cm(const float* __restrict__ Wqkv, const float* __restrict__ Wred) {
    int combo = blockIdx.x;
    int e = combo / 3, r = combo % 3;
    int ii = e / 3, jj = e % 3;
    int w = (r == 0) ? 3 * jj : (r == 1) ? (3 * ii + 1) : (3 * jj + 2);
    int cc0 = blockIdx.y * 64;

    __shared__ float sA[64][65];
    __shared__ float sB[64][65];

    int tx = threadIdx.x & 15, ty = threadIdx.x >> 4;
    float acc[4][4] = {};

    const float* A = Wred + (size_t)e * 64 * 256;
    const float* Bm = Wqkv + (size_t)w * 65536;

    for (int k0 = 0; k0 < 256; k0 += 64) {
        for (int idx = threadIdx.x; idx < 4096; idx += 256) {
            int rr = idx >> 6, cl = idx & 63;
            sA[rr][cl] = A[rr * 256 + k0 + cl];
            sB[rr][cl] = Bm[(k0 + rr) * 256 + cc0 + cl];
        }
        __syncthreads();
#pragma unroll
        for (int kk = 0; kk < 64; kk++) {
            float av[4], bv[4];
#pragma unroll
            for (int u = 0; u < 4; u++) av[u] = sA[ty * 4 + u][kk];
#pragma unroll
            for (int v = 0; v < 4; v++) bv[v] = sB[kk][tx * 4 + v];
#pragma unroll
            for (int u = 0; u < 4; u++)
#pragma unroll
                for (int v = 0; v < 4; v++) acc[u][v] = fmaf(av[u], bv[v], acc[u][v]);
        }
        __syncthreads();
    }
#pragma unroll
    for (int u = 0; u < 4; u++)
#pragma unroll
        for (int v = 0; v < 4; v++)
            g_CMd[combo][cc0 + tx * 4 + v][ty * 4 + u] = make_float2(acc[u][v], acc[u][v]);
}

// ============================================================================
// K2: fused reduced projection + relu + (sum,max) pooling.
//     grid (27, 4 b, 8 hw-chunks of 512), block 512 (16 warps), 1 CTA/SM.
//     smem: 128KB dup-weights + 2x32KB cp.async x stages.
//     Thread: 8 cp channels x 8 hw (4 f32x2 hw-pairs). Pure-smem inner loop.
// ============================================================================
__global__ void __launch_bounds__(512, 1)
k2_pool(const float* __restrict__ xt, const float* __restrict__ xb, const float* __restrict__ xm) {
    extern __shared__ char smraw[];
    ull* wd = (ull*)smraw;              // [256][64] dup weights
    char* sxbase = smraw + 131072;      // 2 x 32768 x-stages

    int combo = blockIdx.x;
    int e = combo / 3, r = combo % 3;
    int ii = e / 3, jj = e % 3;
    int src = (r == 1) ? ii : jj;
    const float* xs = (src == 0) ? xt : (src == 1) ? xb : xm;
    int b = blockIdx.y, chunk = blockIdx.z;
    const float* xg = xs + (size_t)b * NC * NHW + chunk * 512;

    // fill dup weights (contiguous copy)
    {
        const float4* gw = (const float4*)&g_CMd[combo][0][0];  // 8192 float4
        float4* dw = (float4*)wd;
        for (int i = threadIdx.x; i < 8192; i += 512) dw[i] = gw[i];
    }

    int cpg = threadIdx.x >> 6;    // 0..7
    int hwg = threadIdx.x & 63;    // 0..63
    int cp0 = cpg * 8;
    unsigned sx_u32 = smem_u32(sxbase);

    ull acc[8][4];
#pragma unroll
    for (int k = 0; k < 8; k++)
#pragma unroll
        for (int p = 0; p < 4; p++) acc[k][p] = 0ull;

    // prologue: stage 0
    {
#pragma unroll
        for (int p = 0; p < 4; p++) {
            int f = threadIdx.x + p * 512;
            int row = f >> 7, col4 = f & 127;
            cp_async16(sx_u32 + f * 16, xg + (size_t)row * NHW + col4 * 4);
        }
        CP_COMMIT();
    }

    for (int st = 0; st < 16; st++) {
        if (st < 15) {
            int buf = (st + 1) & 1;
#pragma unroll
            for (int p = 0; p < 4; p++) {
                int f = threadIdx.x + p * 512;
                int row = f >> 7, col4 = f & 127;
                cp_async16(sx_u32 + buf * 32768 + f * 16,
                           xg + (size_t)((st + 1) * CHK + row) * NHW + col4 * 4);
            }
        }
        CP_COMMIT();
        CP_WAIT1();
        __syncthreads();

        const ulonglong2* xv = (const ulonglong2*)(sxbase + (st & 1) * 32768);
        const ulonglong2* wv2 = (const ulonglong2*)wd;
#pragma unroll 4
        for (int c = 0; c < CHK; c++) {
            int sc = st * CHK + c;
            ulonglong2 x01 = xv[c * 128 + hwg * 2];
            ulonglong2 x23 = xv[c * 128 + hwg * 2 + 1];
            ull xp[4] = {x01.x, x01.y, x23.x, x23.y};
            int wb = (sc * 64 + cp0) >> 1;
            ulonglong2 w01 = wv2[wb], w23 = wv2[wb + 1], w45 = wv2[wb + 2], w67 = wv2[wb + 3];
            ull wk[8] = {w01.x, w01.y, w23.x, w23.y, w45.x, w45.y, w67.x, w67.y};
#pragma unroll
            for (int k = 0; k < 8; k++)
#pragma unroll
                for (int p = 0; p < 4; p++) acc[k][p] = ffma2(wk[k], xp[p], acc[k][p]);
        }
        __syncthreads();
    }

    // relu + per-thread pool over 8 hw
    float sums[8], maxs[8];
#pragma unroll
    for (int k = 0; k < 8; k++) {
        float s = 0.f, m = 0.f;
#pragma unroll
        for (int p = 0; p < 4; p++) {
            float a, b2;
            upk2(acc[k][p], a, b2);
            float r0 = fmaxf(a, 0.f), r1 = fmaxf(b2, 0.f);
            s += r0 + r1;
            m = fmaxf(m, fmaxf(r0, r1));
        }
        sums[k] = s; maxs[k] = m;
    }

    // block reduction over 64 hw-groups (reuse x-stage smem)
    float* rs = (float*)sxbase;          // [64][64]
    float* rm = rs + 4096;               // [64][64]
#pragma unroll
    for (int k = 0; k < 8; k++) {
        rs[(cp0 + k) * 64 + hwg] = sums[k];
        rm[(cp0 + k) * 64 + hwg] = maxs[k];
    }
    __syncthreads();
    if (threadIdx.x < 64) {
        float s = 0.f, m = 0.f;
        const float* ps = rs + threadIdx.x * 64;
        const float* pm = rm + threadIdx.x * 64;
#pragma unroll 8
        for (int i = 0; i < 64; i++) {
            s += ps[i];
            m = fmaxf(m, pm[i]);
        }
        g_pp_sum[combo][b][chunk][threadIdx.x] = s;
        g_pp_max[combo][b][chunk][threadIdx.x] = m;
    }
}

// ============================================================================
// K3: tiny channel-attention math per (e, b). grid (9,4), block 64.
// ============================================================================
__global__ void k3_attn(const float* __restrict__ Wrec) {
    int e = blockIdx.x, b = blockIdx.y;
    __shared__ float fS[64], gS[64], hS[64], vout[64];
    int j = threadIdx.x;

    {
        float fs = 0.f, fm = 0.f, gs = 0.f, gm = 0.f, hs = 0.f, hm = 0.f;
#pragma unroll
        for (int ch = 0; ch < 8; ch++) {
            fs += g_pp_sum[e * 3 + 1][b][ch][j];  fm = fmaxf(fm, g_pp_max[e * 3 + 1][b][ch][j]);
            gs += g_pp_sum[e * 3 + 0][b][ch][j];  gm = fmaxf(gm, g_pp_max[e * 3 + 0][b][ch][j]);
            hs += g_pp_sum[e * 3 + 2][b][ch][j];  hm = fmaxf(hm, g_pp_max[e * 3 + 2][b][ch][j]);
        }
        const float inv = 1.f / 4096.f;
        fS[j] = fs * inv + fm;
        gS[j] = gs * inv + gm;
        hS[j] = hs * inv + hm;
    }
    __syncthreads();

    float gj = gS[j];
    float mx = -1e30f;
#pragma unroll 8
    for (int i = 0; i < 64; i++) mx = fmaxf(mx, fS[i] * gj);
    float den = 0.f, num = 0.f;
#pragma unroll 8
    for (int i = 0; i < 64; i++) {
        float ev = expf(fS[i] * gj - mx);
        den += ev;
        num += hS[i] * ev;
    }
    vout[j] = num / den;
    __syncthreads();

    for (int c = j; c < 256; c += 64) {
        const float* wr = Wrec + ((size_t)e * 256 + c) * 64;
        float acc = 0.f;
#pragma unroll 8
        for (int q = 0; q < 64; q++) acc = fmaf(vout[q], wr[q], acc);
        g_o[e][b][c] = 1.f / (1.f + expf(-acc));
    }
}

// ============================================================================
// K5: output GEMM with on-the-fly gated dup-weight tile.
//     grid (4 ct, 4 b, 8 hz of 512 hw), block 512. Same staged inner loop,
//     accumulating across 3 sources.
// ============================================================================
__global__ void __launch_bounds__(512, 1)
k5_out(const float* __restrict__ xt, const float* __restrict__ xb, const float* __restrict__ xm,
       const float* __restrict__ Wqkv, float* __restrict__ out) {
    extern __shared__ char smraw[];
    ull* wd = (ull*)smraw;              // [256 cin][64 lc] dup gated weights
    char* sxbase = smraw + 131072;      // tmp [64][257] floats during build; 2x32KB x-stages
    __shared__ float sAc[64], sBc[64];

    int ct = blockIdx.x, b = blockIdx.y, hz = blockIdx.z;
    int cpg = threadIdx.x >> 6, hwg = threadIdx.x & 63;
    int cp0 = cpg * 8;
    unsigned sx_u32 = smem_u32(sxbase);

    ull acc[8][4];
#pragma unroll
    for (int k = 0; k < 8; k++)
#pragma unroll
        for (int p = 0; p < 4; p++) acc[k][p] = 0ull;

    for (int s = 0; s < 3; s++) {
        CP_WAIT0();
        __syncthreads();
        if (threadIdx.x < 64) {
            int c = ct * 64 + threadIdx.x;
            sAc[threadIdx.x] = g_o[s][b][c] + g_o[s + 3][b][c] + g_o[s + 6][b][c];
            sBc[threadIdx.x] = g_o[3 * s][b][c] + g_o[3 * s + 1][b][c] + g_o[3 * s + 2][b][c];
        }
        __syncthreads();

        // build gated tile: coalesced read -> padded tmp -> transposed dup write
        float* tmp = (float*)sxbase;  // [64][257]
        const float* Wq = Wqkv + (size_t)(3 * s) * 65536 + (size_t)ct * 64 * 256;
        const float* Wk = Wq + 65536;
        const float* Wv = Wk + 65536;
        for (int idx = threadIdx.x; idx < 16384; idx += 512) {
            int lc = idx >> 8, cin = idx & 255;
            float w = sAc[lc] * (Wq[lc * 256 + cin] + Wv[lc * 256 + cin]) + sBc[lc] * Wk[lc * 256 + cin];
            tmp[lc * 257 + cin] = w;
        }
        __syncthreads();
        for (int idx = threadIdx.x; idx < 16384; idx += 512) {
            int cin = idx >> 6, lc = idx & 63;
            float w = tmp[lc * 257 + cin];
            wd[cin * 64 + lc] = pk2(w, w);
        }
        __syncthreads();

        const float* xs = (s == 0) ? xt : (s == 1) ? xb : xm;
        const float* xg = xs + (size_t)b * NC * NHW + hz * 512;

        // stage 0 prologue
#pragma unroll
        for (int p = 0; p < 4; p++) {
            int f = threadIdx.x + p * 512;
            int row = f >> 7, col4 = f & 127;
            cp_async16(sx_u32 + f * 16, xg + (size_t)row * NHW + col4 * 4);
        }
        CP_COMMIT();

        for (int st = 0; st < 16; st++) {
            if (st < 15) {
                int buf = (st + 1) & 1;
#pragma unroll
                for (int p = 0; p < 4; p++) {
                    int f = threadIdx.x + p * 512;
                    int row = f >> 7, col4 = f & 127;
                    cp_async16(sx_u32 + buf * 32768 + f * 16,
                               xg + (size_t)((st + 1) * CHK + row) * NHW + col4 * 4);
                }
            }
            CP_COMMIT();
            CP_WAIT1();
            __syncthreads();

            const ulonglong2* xv = (const ulonglong2*)(sxbase + (st & 1) * 32768);
            const ulonglong2* wv2 = (const ulonglong2*)wd;
#pragma unroll 4
            for (int c = 0; c < CHK; c++) {
                int sc = st * CHK + c;
                ulonglong2 x01 = xv[c * 128 + hwg * 2];
                ulonglong2 x23 = xv[c * 128 + hwg * 2 + 1];
                ull xp[4] = {x01.x, x01.y, x23.x, x23.y};
                int wb = (sc * 64 + cp0) >> 1;
                ulonglong2 w01 = wv2[wb], w23 = wv2[wb + 1], w45 = wv2[wb + 2], w67 = wv2[wb + 3];
                ull wk[8] = {w01.x, w01.y, w23.x, w23.y, w45.x, w45.y, w67.x, w67.y};
#pragma unroll
                for (int k = 0; k < 8; k++)
#pragma unroll
                    for (int p = 0; p < 4; p++) acc[k][p] = ffma2(wk[k], xp[p], acc[k][p]);
            }
            __syncthreads();
        }
    }

    // store: per channel, 8 hw = 2 float4
    float4* out4 = (float4*)out;
#pragma unroll
    for (int k = 0; k < 8; k++) {
        int ch = ct * 64 + cp0 + k;
        size_t ofs = ((size_t)b * NC + ch) * NHW4 + hz * 128 + hwg * 2;
        union { ull u[2]; float4 f; } t0, t1;
        t0.u[0] = acc[k][0]; t0.u[1] = acc[k][1];
        t1.u[0] = acc[k][2]; t1.u[1] = acc[k][3];
        out4[ofs] = t0.f;
        out4[ofs + 1] = t1.f;
    }
}

// ============================================================================
extern "C" void kernel_launch(void* const* d_in, const int* in_sizes, int n_in,
                              void* d_out, int out_size) {
    (void)in_sizes; (void)n_in; (void)out_size;
    const float* t    = (const float*)d_in[0];
    const float* bb   = (const float*)d_in[1];
    const float* mm   = (const float*)d_in[2];
    const float* Wqkv = (const float*)d_in[3];
    const float* Wred = (const float*)d_in[4];
    const float* Wrec = (const float*)d_in[5];
    float* out = (float*)d_out;

    cudaFuncSetAttribute(k2_pool, cudaFuncAttributeMaxDynamicSharedMemorySize, 196608);
    cudaFuncSetAttribute(k5_out, cudaFuncAttributeMaxDynamicSharedMemorySize, 196864);

    k1_cm<<<dim3(27, 4), 256>>>(Wqkv, Wred);
    k2_pool<<<dim3(27, 4, 8), 512, 196608>>>(t, bb, mm);
    k3_attn<<<dim3(9, 4), 64>>>(Wrec);
    k5_out<<<dim3(4, 4, 8), 512, 196864>>>(t, bb, mm, Wqkv, out);
}

// round 5
// speedup vs baseline: 2.8179x; 1.9951x over previous
#include <cuda_runtime.h>
#include <cuda_bf16.h>
#include <cstdint>

typedef unsigned int u32;
typedef unsigned long long u64;

#define NB 4
#define NC 256
#define NHW 4096

// ---------------- device scratch ----------------
__device__ __align__(16) __nv_bfloat16 g_CM_hi[27][64][256];  // split combined matrices
__device__ __align__(16) __nv_bfloat16 g_CM_lo[27][64][256];
__device__ float g_pp_sum[27][4][16][64];
__device__ float g_pp_max[27][4][16][64];
__device__ float g_o[9][4][256];
// x transposed + bf16-split: [src*4+b][hw 4096][cin 256]
__device__ __align__(16) __nv_bfloat16 g_xT_hi[12u * 4096u * 256u];
__device__ __align__(16) __nv_bfloat16 g_xT_lo[12u * 4096u * 256u];
// gated output weights, split: [b][ct][s][hi/lo][128][256]
__device__ __align__(16) __nv_bfloat16 g_W5[4 * 2 * 3 * 2 * 128 * 256];

// ---------------- helpers ----------------
static __device__ __forceinline__ u32 smem_u32(const void* p) {
    return (u32)__cvta_generic_to_shared(p);
}
static __device__ __forceinline__ void cp16(u32 d, const void* s) {
    asm volatile("cp.async.cg.shared.global [%0], [%1], 16;" :: "r"(d), "l"(s));
}
#define CP_COMMIT() asm volatile("cp.async.commit_group;" ::: "memory")
#define CP_WAIT1()  asm volatile("cp.async.wait_group 1;" ::: "memory")
#define CP_WAIT0()  asm volatile("cp.async.wait_group 0;" ::: "memory")

static __device__ __forceinline__ void ldsm4(u32* r, u32 a) {
    asm volatile("ldmatrix.sync.aligned.m8n8.x4.shared.b16 {%0,%1,%2,%3}, [%4];"
                 : "=r"(r[0]), "=r"(r[1]), "=r"(r[2]), "=r"(r[3]) : "r"(a));
}
static __device__ __forceinline__ void mma16816(float* d, const u32* a, const u32* b) {
    asm volatile(
        "mma.sync.aligned.m16n8k16.row.col.f32.bf16.bf16.f32 "
        "{%0,%1,%2,%3},{%4,%5,%6,%7},{%8,%9},{%0,%1,%2,%3};"
        : "+f"(d[0]), "+f"(d[1]), "+f"(d[2]), "+f"(d[3])
        : "r"(a[0]), "r"(a[1]), "r"(a[2]), "r"(a[3]), "r"(b[0]), "r"(b[1]));
}
static __device__ __forceinline__ void split_bf16(float v, __nv_bfloat16& h, __nv_bfloat16& l) {
    h = __float2bfloat16_rn(v);
    l = __float2bfloat16_rn(v - __bfloat162float(h));
}

// smem layout (bytes). Rows padded to 264 bf16 = 528B (odd 16B stride -> no LDSM conflicts)
#define ROWB   528
#define SA_HI  0
#define SA_LO  67584          // 128*528
#define SM_B   135168         // A total 132KB
#define BBUF   33792          // per buffer: hi 16896 + lo 16896
#define SMEMSZ 202752         // 135168 + 2*33792

// ============================================================================
// K0: transpose + bf16-split x -> g_xT_hi/lo [src*4+b][hw][cin]
// ============================================================================
__global__ void k0_split(const float* __restrict__ xt, const float* __restrict__ xb,
                         const float* __restrict__ xm) {
    int sb = blockIdx.x;
    int src = sb >> 2, b = sb & 3;
    const float* xs = (src == 0) ? xt : (src == 1) ? xb : xm;
    int cin0 = blockIdx.y * 32, hw0 = blockIdx.z * 256;
    __shared__ float s[32][257];
    const float* base = xs + ((size_t)b * NC + cin0) * NHW + hw0;
    for (int i = threadIdx.x; i < 32 * 256; i += 256) {
        int r = i >> 8, c = i & 255;
        s[r][c] = base[(size_t)r * NHW + c];
    }
    __syncthreads();
    int t = threadIdx.x;
    u32 hb[16], lb[16];
#pragma unroll
    for (int m = 0; m < 16; m++) {
        __nv_bfloat16 h0, l0, h1, l1;
        split_bf16(s[2 * m][t], h0, l0);
        split_bf16(s[2 * m + 1][t], h1, l1);
        hb[m] = (u32)__bfloat16_as_ushort(h0) | ((u32)__bfloat16_as_ushort(h1) << 16);
        lb[m] = (u32)__bfloat16_as_ushort(l0) | ((u32)__bfloat16_as_ushort(l1) << 16);
    }
    size_t ro = ((size_t)sb * 4096 + hw0 + t) * 256 + cin0;
    uint4* dh = (uint4*)&g_xT_hi[ro];
    uint4* dl = (uint4*)&g_xT_lo[ro];
#pragma unroll
    for (int q = 0; q < 4; q++) {
        dh[q] = make_uint4(hb[4 * q], hb[4 * q + 1], hb[4 * q + 2], hb[4 * q + 3]);
        dl[q] = make_uint4(lb[4 * q], lb[4 * q + 1], lb[4 * q + 2], lb[4 * q + 3]);
    }
}

// ============================================================================
// K1: combined matrices Wred[e]@Wqkv[w] -> split bf16 g_CM_hi/lo[combo][cp][cin]
// ============================================================================
__global__ void k1_cm(const float* __restrict__ Wqkv, const float* __restrict__ Wred) {
    int combo = blockIdx.x;
    int e = combo / 3, r = combo % 3;
    int ii = e / 3, jj = e % 3;
    int w = (r == 0) ? 3 * jj : (r == 1) ? (3 * ii + 1) : (3 * jj + 2);
    int cc0 = blockIdx.y * 64;

    __shared__ float sA[64][65];
    __shared__ float sB[64][65];

    int tx = threadIdx.x & 15, ty = threadIdx.x >> 4;
    float acc[4][4] = {};

    const float* A = Wred + (size_t)e * 64 * 256;
    const float* Bm = Wqkv + (size_t)w * 65536;

    for (int k0 = 0; k0 < 256; k0 += 64) {
        for (int idx = threadIdx.x; idx < 4096; idx += 256) {
            int rr = idx >> 6, cl = idx & 63;
            sA[rr][cl] = A[rr * 256 + k0 + cl];
            sB[rr][cl] = Bm[(k0 + rr) * 256 + cc0 + cl];
        }
        __syncthreads();
#pragma unroll
        for (int kk = 0; kk < 64; kk++) {
            float av[4], bv[4];
#pragma unroll
            for (int u = 0; u < 4; u++) av[u] = sA[ty * 4 + u][kk];
#pragma unroll
            for (int v = 0; v < 4; v++) bv[v] = sB[kk][tx * 4 + v];
#pragma unroll
            for (int u = 0; u < 4; u++)
#pragma unroll
                for (int v = 0; v < 4; v++) acc[u][v] = fmaf(av[u], bv[v], acc[u][v]);
        }
        __syncthreads();
    }
#pragma unroll
    for (int u = 0; u < 4; u++)
#pragma unroll
        for (int v = 0; v < 4; v++) {
            __nv_bfloat16 h, l;
            split_bf16(acc[u][v], h, l);
            g_CM_hi[combo][ty * 4 + u][cc0 + tx * 4 + v] = h;
            g_CM_lo[combo][ty * 4 + u][cc0 + tx * 4 + v] = l;
        }
}

// ---- B tile loader: 32 hw rows, hi+lo, into padded smem buffer ----
static __device__ __forceinline__ void load_B32(
    u32 smb, int buf, const __nv_bfloat16* XH, const __nv_bfloat16* XL, int hw0, int tid) {
    u32 dhi = smb + SM_B + buf * BBUF;
    u32 dlo = dhi + 16896;
#pragma unroll
    for (int i = 0; i < 4; i++) {
        int f = tid + i * 256;
        int row = f >> 5, c = f & 31;
        size_t so = (size_t)(hw0 + row) * 256 + c * 8;
        cp16(dhi + row * ROWB + c * 16, XH + so);
        cp16(dlo + row * ROWB + c * 16, XL + so);
    }
}

// ============================================================================
// K2: HMMA reduced projection + relu + pool.
//     grid (15 = 3src*5mt, 4 b, 16 hw-chunks of 256), block 256 (8 warps).
//     CTA tile: 128 rows (2 combos) x 32 hw per step, 8 steps.
// ============================================================================
__global__ void __launch_bounds__(256, 1)
k2_mma() {
    extern __shared__ __align__(16) char sm[];
    u32 smb = smem_u32(sm);

    int tid = threadIdx.x, wid = tid >> 5, lane = tid & 31;
    int src = blockIdx.x / 5, mt = blockIdx.x % 5;
    int b = blockIdx.y, z = blockIdx.z;

    int list[9];
    int n = 0;
    for (int combo = 0; combo < 27; combo++) {
        int e = combo / 3, r = combo % 3;
        int sc = (r == 1) ? e / 3 : e % 3;
        if (sc == src) list[n++] = combo;
    }
    int c0 = list[2 * mt];
    bool has1 = (2 * mt + 1) < 9;
    int c1 = has1 ? list[2 * mt + 1] : c0;

    const __nv_bfloat16* XH = g_xT_hi + (size_t)(src * 4 + b) * 4096 * 256;
    const __nv_bfloat16* XL = g_xT_lo + (size_t)(src * 4 + b) * 4096 * 256;

    // A load: 128 rows (c0 rows 0-63, c1 rows 64-127), hi+lo
#pragma unroll
    for (int i = 0; i < 16; i++) {
        int f = tid + i * 256;
        int row = f >> 5, c = f & 31;
        int cb = (row < 64) ? c0 : c1;
        size_t so = ((size_t)cb * 64 + (row & 63)) * 256 + c * 8;
        cp16(smb + SA_HI + row * ROWB + c * 16, &g_CM_hi[0][0][0] + so);
        cp16(smb + SA_LO + row * ROWB + c * 16, &g_CM_lo[0][0][0] + so);
    }
    CP_COMMIT();

    load_B32(smb, 0, XH, XL, z * 256, tid);
    CP_COMMIT();

    int mwarp = wid >> 1, nwarp = wid & 1;
    int R0 = mwarp * 32;
    int H = nwarp * 16;

    // lane-resolved base addresses
    u32 aoff = (u32)(R0 + (lane & 15)) * ROWB + (lane >> 4) * 16;
    u32 aHi = smb + SA_HI + aoff;
    u32 aLo = smb + SA_LO + aoff;
    u32 boff = (u32)(H + (lane & 7) + ((lane >= 16) ? 8 : 0)) * ROWB + ((lane & 8) ? 16 : 0);

    float psum[2][2] = {}, pmax[2][2] = {};

    for (int step = 0; step < 8; step++) {
        if (step < 7) {
            load_B32(smb, (step + 1) & 1, XH, XL, z * 256 + (step + 1) * 32, tid);
            CP_COMMIT();
            CP_WAIT1();
        } else {
            CP_WAIT0();
        }
        __syncthreads();

        u32 bHi = smb + SM_B + (step & 1) * BBUF + boff;
        u32 bLo = bHi + 16896;

        float acc[2][2][4] = {};
#pragma unroll
        for (int kk = 0; kk < 16; kk++) {
            u32 kb = kk * 32;
            u32 ah0[4], ah1[4], al0[4], al1[4], bh[4], bl[4];
            ldsm4(ah0, aHi + kb);
            ldsm4(ah1, aHi + 16 * ROWB + kb);
            ldsm4(al0, aLo + kb);
            ldsm4(al1, aLo + 16 * ROWB + kb);
            ldsm4(bh, bHi + kb);
            ldsm4(bl, bLo + kb);
            mma16816(acc[0][0], ah0, bh);
            mma16816(acc[0][0], al0, bh);
            mma16816(acc[0][0], ah0, bl);
            mma16816(acc[0][1], ah0, bh + 2);
            mma16816(acc[0][1], al0, bh + 2);
            mma16816(acc[0][1], ah0, bl + 2);
            mma16816(acc[1][0], ah1, bh);
            mma16816(acc[1][0], al1, bh);
            mma16816(acc[1][0], ah1, bl);
            mma16816(acc[1][1], ah1, bh + 2);
            mma16816(acc[1][1], al1, bh + 2);
            mma16816(acc[1][1], ah1, bl + 2);
        }
        // relu + pool
#pragma unroll
        for (int m = 0; m < 2; m++)
#pragma unroll
            for (int nt = 0; nt < 2; nt++) {
                float r0 = fmaxf(acc[m][nt][0], 0.f), r1 = fmaxf(acc[m][nt][1], 0.f);
                float r2 = fmaxf(acc[m][nt][2], 0.f), r3 = fmaxf(acc[m][nt][3], 0.f);
                psum[m][0] += r0 + r1;
                psum[m][1] += r2 + r3;
                pmax[m][0] = fmaxf(pmax[m][0], fmaxf(r0, r1));
                pmax[m][1] = fmaxf(pmax[m][1], fmaxf(r2, r3));
            }
        __syncthreads();
    }

    // reduce over the 4 lanes of each quad (cols 2t,2t+1)
#pragma unroll
    for (int m = 0; m < 2; m++)
#pragma unroll
        for (int h = 0; h < 2; h++) {
#pragma unroll
            for (int off = 1; off <= 2; off <<= 1) {
                psum[m][h] += __shfl_xor_sync(0xffffffffu, psum[m][h], off);
                pmax[m][h] = fmaxf(pmax[m][h], __shfl_xor_sync(0xffffffffu, pmax[m][h], off));
            }
        }

    float* ps = (float*)(sm + SM_B);        // [128][2]
    float* pm = ps + 256;
    if ((lane & 3) == 0) {
        int g = lane >> 2;
#pragma unroll
        for (int m = 0; m < 2; m++)
#pragma unroll
            for (int h = 0; h < 2; h++) {
                int row = R0 + m * 16 + h * 8 + g;
                ps[row * 2 + nwarp] = psum[m][h];
                pm[row * 2 + nwarp] = pmax[m][h];
            }
    }
    __syncthreads();
    if (tid < 128) {
        float s = ps[tid * 2] + ps[tid * 2 + 1];
        float m = fmaxf(pm[tid * 2], pm[tid * 2 + 1]);
        if (tid < 64 || has1) {
            int cb = (tid < 64) ? c0 : c1;
            g_pp_sum[cb][b][z][tid & 63] = s;
            g_pp_max[cb][b][z][tid & 63] = m;
        }
    }
}

// ============================================================================
// K3: channel-attention math per (e, b). grid (9,4), block 64.
// ============================================================================
__global__ void k3_attn(const float* __restrict__ Wrec) {
    int e = blockIdx.x, b = blockIdx.y;
    __shared__ float fS[64], gS[64], hS[64], vout[64];
    int j = threadIdx.x;
    {
        float fs = 0.f, fm = 0.f, gs = 0.f, gm = 0.f, hs = 0.f, hm = 0.f;
#pragma unroll
        for (int ch = 0; ch < 16; ch++) {
            fs += g_pp_sum[e * 3 + 1][b][ch][j];  fm = fmaxf(fm, g_pp_max[e * 3 + 1][b][ch][j]);
            gs += g_pp_sum[e * 3 + 0][b][ch][j];  gm = fmaxf(gm, g_pp_max[e * 3 + 0][b][ch][j]);
            hs += g_pp_sum[e * 3 + 2][b][ch][j];  hm = fmaxf(hm, g_pp_max[e * 3 + 2][b][ch][j]);
        }
        const float inv = 1.f / 4096.f;
        fS[j] = fs * inv + fm;
        gS[j] = gs * inv + gm;
        hS[j] = hs * inv + hm;
    }
    __syncthreads();

    float gj = gS[j];
    float mx = -1e30f;
#pragma unroll 8
    for (int i = 0; i < 64; i++) mx = fmaxf(mx, fS[i] * gj);
    float den = 0.f, num = 0.f;
#pragma unroll 8
    for (int i = 0; i < 64; i++) {
        float ev = expf(fS[i] * gj - mx);
        den += ev;
        num += hS[i] * ev;
    }
    vout[j] = num / den;
    __syncthreads();

    for (int c = j; c < 256; c += 64) {
        const float* wr = Wrec + ((size_t)e * 256 + c) * 64;
        float acc = 0.f;
#pragma unroll 8
        for (int q = 0; q < 64; q++) acc = fmaf(vout[q], wr[q], acc);
        g_o[e][b][c] = 1.f / (1.f + expf(-acc));
    }
}

// ============================================================================
// K4: build gated split weights g_W5[b][ct][s][hi/lo][128][256]
//     grid (4, 2, 3), block 256.
// ============================================================================
__global__ void k4_w5(const float* __restrict__ Wqkv) {
    int b = blockIdx.x, ct = blockIdx.y, s = blockIdx.z;
    __shared__ float sA[128], sB[128];
    if (threadIdx.x < 128) {
        int c = ct * 128 + threadIdx.x;
        sA[threadIdx.x] = g_o[s][b][c] + g_o[s + 3][b][c] + g_o[s + 6][b][c];
        sB[threadIdx.x] = g_o[3 * s][b][c] + g_o[3 * s + 1][b][c] + g_o[3 * s + 2][b][c];
    }
    __syncthreads();
    const float* Wq = Wqkv + (size_t)(3 * s) * 65536 + (size_t)ct * 128 * 256;
    const float* Wk = Wq + 65536;
    const float* Wv = Wk + 65536;
    size_t base = (((size_t)(b * 2 + ct) * 3 + s) * 2) * 128 * 256;
    for (int i = threadIdx.x; i < 128 * 256; i += 256) {
        int row = i >> 8, cin = i & 255;
        float w = sA[row] * (Wq[row * 256 + cin] + Wv[row * 256 + cin])
                + sB[row] * Wk[row * 256 + cin];
        __nv_bfloat16 h, l;
        split_bf16(w, h, l);
        g_W5[base + i] = h;
        g_W5[base + 128 * 256 + i] = l;
    }
}

// ============================================================================
// K5: HMMA output GEMM, accumulate 3 sources in registers.
//     grid (2 ct, 4 b, 32 hz of 128 hw), block 256 (8 warps).
//     Per s: cp.async A_s; 4 B-steps of 32 hw. acc[4 steps][2][2][4].
// ============================================================================
__global__ void __launch_bounds__(256, 1)
k5_mma(float* __restrict__ out) {
    extern __shared__ __align__(16) char sm[];
    u32 smb = smem_u32(sm);

    int tid = threadIdx.x, wid = tid >> 5, lane = tid & 31;
    int ct = blockIdx.x, b = blockIdx.y, hz = blockIdx.z;

    int mwarp = wid >> 1, nwarp = wid & 1;
    int R0 = mwarp * 32;
    int H = nwarp * 16;

    u32 aoff = (u32)(R0 + (lane & 15)) * ROWB + (lane >> 4) * 16;
    u32 aHi = smb + SA_HI + aoff;
    u32 aLo = smb + SA_LO + aoff;
    u32 boff = (u32)(H + (lane & 7) + ((lane >= 16) ? 8 : 0)) * ROWB + ((lane & 8) ? 16 : 0);

    float acc[4][2][2][4] = {};

    for (int s = 0; s < 3; s++) {
        // A_s (hi+lo)
        const __nv_bfloat16* WA = g_W5 + (((size_t)(b * 2 + ct) * 3 + s) * 2) * 128 * 256;
#pragma unroll
        for (int i = 0; i < 16; i++) {
            int f = tid + i * 256;
            int row = f >> 5, c = f & 31;
            size_t so = (size_t)row * 256 + c * 8;
            cp16(smb + SA_HI + row * ROWB + c * 16, WA + so);
            cp16(smb + SA_LO + row * ROWB + c * 16, WA + 128 * 256 + so);
        }
        CP_COMMIT();

        const __nv_bfloat16* XH = g_xT_hi + (size_t)(s * 4 + b) * 4096 * 256;
        const __nv_bfloat16* XL = g_xT_lo + (size_t)(s * 4 + b) * 4096 * 256;

        load_B32(smb, 0, XH, XL, hz * 128, tid);
        CP_COMMIT();

#pragma unroll
        for (int step = 0; step < 4; step++) {
            if (step < 3) {
                load_B32(smb, (step + 1) & 1, XH, XL, hz * 128 + (step + 1) * 32, tid);
                CP_COMMIT();
                CP_WAIT1();
            } else {
                CP_WAIT0();
            }
            __syncthreads();

            u32 bHi = smb + SM_B + (step & 1) * BBUF + boff;
            u32 bLo = bHi + 16896;
#pragma unroll
            for (int kk = 0; kk < 16; kk++) {
                u32 kb = kk * 32;
                u32 ah0[4], ah1[4], al0[4], al1[4], bh[4], bl[4];
                ldsm4(ah0, aHi + kb);
                ldsm4(ah1, aHi + 16 * ROWB + kb);
                ldsm4(al0, aLo + kb);
                ldsm4(al1, aLo + 16 * ROWB + kb);
                ldsm4(bh, bHi + kb);
                ldsm4(bl, bLo + kb);
                mma16816(acc[step][0][0], ah0, bh);
                mma16816(acc[step][0][0], al0, bh);
                mma16816(acc[step][0][0], ah0, bl);
                mma16816(acc[step][0][1], ah0, bh + 2);
                mma16816(acc[step][0][1], al0, bh + 2);
                mma16816(acc[step][0][1], ah0, bl + 2);
                mma16816(acc[step][1][0], ah1, bh);
                mma16816(acc[step][1][0], al1, bh);
                mma16816(acc[step][1][0], ah1, bl);
                mma16816(acc[step][1][1], ah1, bh + 2);
                mma16816(acc[step][1][1], al1, bh + 2);
                mma16816(acc[step][1][1], ah1, bl + 2);
            }
            __syncthreads();
        }
    }

    // store
    int g = lane >> 2, t = lane & 3;
#pragma unroll
    for (int step = 0; step < 4; step++)
#pragma unroll
        for (int m = 0; m < 2; m++)
#pragma unroll
            for (int nt = 0; nt < 2; nt++) {
                int ch = ct * 128 + R0 + m * 16 + g;
                int col = hz * 128 + step * 32 + H + nt * 8 + 2 * t;
                float2* p0 = (float2*)(out + ((size_t)b * NC + ch) * NHW + col);
                float2* p1 = (float2*)(out + ((size_t)b * NC + ch + 8) * NHW + col);
                *p0 = make_float2(acc[step][m][nt][0], acc[step][m][nt][1]);
                *p1 = make_float2(acc[step][m][nt][2], acc[step][m][nt][3]);
            }
}

// ============================================================================
extern "C" void kernel_launch(void* const* d_in, const int* in_sizes, int n_in,
                              void* d_out, int out_size) {
    (void)in_sizes; (void)n_in; (void)out_size;
    const float* t    = (const float*)d_in[0];
    const float* bb   = (const float*)d_in[1];
    const float* mm   = (const float*)d_in[2];
    const float* Wqkv = (const float*)d_in[3];
    const float* Wred = (const float*)d_in[4];
    const float* Wrec = (const float*)d_in[5];
    float* out = (float*)d_out;

    cudaFuncSetAttribute(k2_mma, cudaFuncAttributeMaxDynamicSharedMemorySize, SMEMSZ);
    cudaFuncSetAttribute(k5_mma, cudaFuncAttributeMaxDynamicSharedMemorySize, SMEMSZ);

    k0_split<<<dim3(12, 8, 16), 256>>>(t, bb, mm);
    k1_cm<<<dim3(27, 4), 256>>>(Wqkv, Wred);
    k2_mma<<<dim3(15, 4, 16), 256, SMEMSZ>>>();
    k3_attn<<<dim3(9, 4), 64>>>(Wrec);
    k4_w5<<<dim3(4, 2, 3), 256>>>(Wqkv);
    k5_mma<<<dim3(2, 4, 32), 256, SMEMSZ>>>(out);
}

// round 6
// speedup vs baseline: 3.4349x; 1.2190x over previous
#include <cuda_runtime.h>
#include <cuda_fp16.h>
#include <cstdint>

typedef unsigned int u32;
typedef unsigned long long u64;

#define NB 4
#define NC 256
#define NHW 4096

// ---------------- device scratch ----------------
__device__ __align__(16) __half g_CM_hi[27][64][256];  // split combined matrices
__device__ __align__(16) __half g_CM_lo[27][64][256];
__device__ float g_pp_sum[27][4][16][64];
__device__ float g_pp_max[27][4][16][64];
__device__ float g_o[9][4][256];
// x transposed + fp16-split: [src*4+b][hw 4096][cin 256]
__device__ __align__(16) __half g_xT_hi[12u * 4096u * 256u];
__device__ __align__(16) __half g_xT_lo[12u * 4096u * 256u];
// gated output weights, split: [b][ct][s][hi/lo][128][256]
__device__ __align__(16) __half g_W5[4 * 2 * 3 * 2 * 128 * 256];

// ---------------- helpers ----------------
static __device__ __forceinline__ u32 smem_u32(const void* p) {
    return (u32)__cvta_generic_to_shared(p);
}
static __device__ __forceinline__ void cp16(u32 d, const void* s) {
    asm volatile("cp.async.cg.shared.global [%0], [%1], 16;" :: "r"(d), "l"(s));
}
#define CP_COMMIT() asm volatile("cp.async.commit_group;" ::: "memory")
#define CP_WAIT1()  asm volatile("cp.async.wait_group 1;" ::: "memory")
#define CP_WAIT0()  asm volatile("cp.async.wait_group 0;" ::: "memory")

static __device__ __forceinline__ void ldsm4(u32* r, u32 a) {
    asm volatile("ldmatrix.sync.aligned.m8n8.x4.shared.b16 {%0,%1,%2,%3}, [%4];"
                 : "=r"(r[0]), "=r"(r[1]), "=r"(r[2]), "=r"(r[3]) : "r"(a));
}
static __device__ __forceinline__ void mma16816(float* d, const u32* a, const u32* b) {
    asm volatile(
        "mma.sync.aligned.m16n8k16.row.col.f32.f16.f16.f32 "
        "{%0,%1,%2,%3},{%4,%5,%6,%7},{%8,%9},{%0,%1,%2,%3};"
        : "+f"(d[0]), "+f"(d[1]), "+f"(d[2]), "+f"(d[3])
        : "r"(a[0]), "r"(a[1]), "r"(a[2]), "r"(a[3]), "r"(b[0]), "r"(b[1]));
}
static __device__ __forceinline__ void split_h(float v, __half& h, __half& l) {
    h = __float2half_rn(v);
    l = __float2half_rn(v - __half2float(h));
}

// smem layout (bytes). Rows padded: 256 fp16 = 512B + 16B pad = 528B
#define ROWB   528
#define SA_HI  0
#define SA_LO  67584           // 128*528
#define SM_B   135168
#define BBUF   33792           // 64 rows * 528
#define SMEMSZ 202752          // 135168 + 2*33792

// ============================================================================
// K0: transpose + fp16-split x -> g_xT_hi/lo [src*4+b][hw][cin]
// ============================================================================
__global__ void k0_split(const float* __restrict__ xt, const float* __restrict__ xb,
                         const float* __restrict__ xm) {
    int sb = blockIdx.x;
    int src = sb >> 2, b = sb & 3;
    const float* xs = (src == 0) ? xt : (src == 1) ? xb : xm;
    int cin0 = blockIdx.y * 32, hw0 = blockIdx.z * 256;
    __shared__ float s[32][257];
    const float* base = xs + ((size_t)b * NC + cin0) * NHW + hw0;
    for (int i = threadIdx.x; i < 32 * 256; i += 256) {
        int r = i >> 8, c = i & 255;
        s[r][c] = base[(size_t)r * NHW + c];
    }
    __syncthreads();
    int t = threadIdx.x;
    u32 hb[16], lb[16];
#pragma unroll
    for (int m = 0; m < 16; m++) {
        __half h0, l0, h1, l1;
        split_h(s[2 * m][t], h0, l0);
        split_h(s[2 * m + 1][t], h1, l1);
        hb[m] = (u32)__half_as_ushort(h0) | ((u32)__half_as_ushort(h1) << 16);
        lb[m] = (u32)__half_as_ushort(l0) | ((u32)__half_as_ushort(l1) << 16);
    }
    size_t ro = ((size_t)sb * 4096 + hw0 + t) * 256 + cin0;
    uint4* dh = (uint4*)&g_xT_hi[ro];
    uint4* dl = (uint4*)&g_xT_lo[ro];
#pragma unroll
    for (int q = 0; q < 4; q++) {
        dh[q] = make_uint4(hb[4 * q], hb[4 * q + 1], hb[4 * q + 2], hb[4 * q + 3]);
        dl[q] = make_uint4(lb[4 * q], lb[4 * q + 1], lb[4 * q + 2], lb[4 * q + 3]);
    }
}

// ============================================================================
// K1: combined matrices Wred[e]@Wqkv[w] -> split fp16 g_CM_hi/lo[combo][cp][cin]
// ============================================================================
__global__ void k1_cm(const float* __restrict__ Wqkv, const float* __restrict__ Wred) {
    int combo = blockIdx.x;
    int e = combo / 3, r = combo % 3;
    int ii = e / 3, jj = e % 3;
    int w = (r == 0) ? 3 * jj : (r == 1) ? (3 * ii + 1) : (3 * jj + 2);
    int cc0 = blockIdx.y * 64;

    __shared__ float sA[64][65];
    __shared__ float sB[64][65];

    int tx = threadIdx.x & 15, ty = threadIdx.x >> 4;
    float acc[4][4] = {};

    const float* A = Wred + (size_t)e * 64 * 256;
    const float* Bm = Wqkv + (size_t)w * 65536;

    for (int k0 = 0; k0 < 256; k0 += 64) {
        for (int idx = threadIdx.x; idx < 4096; idx += 256) {
            int rr = idx >> 6, cl = idx & 63;
            sA[rr][cl] = A[rr * 256 + k0 + cl];
            sB[rr][cl] = Bm[(k0 + rr) * 256 + cc0 + cl];
        }
        __syncthreads();
#pragma unroll
        for (int kk = 0; kk < 64; kk++) {
            float av[4], bv[4];
#pragma unroll
            for (int u = 0; u < 4; u++) av[u] = sA[ty * 4 + u][kk];
#pragma unroll
            for (int v = 0; v < 4; v++) bv[v] = sB[kk][tx * 4 + v];
#pragma unroll
            for (int u = 0; u < 4; u++)
#pragma unroll
                for (int v = 0; v < 4; v++) acc[u][v] = fmaf(av[u], bv[v], acc[u][v]);
        }
        __syncthreads();
    }
#pragma unroll
    for (int u = 0; u < 4; u++)
#pragma unroll
        for (int v = 0; v < 4; v++) {
            __half h, l;
            split_h(acc[u][v], h, l);
            g_CM_hi[combo][ty * 4 + u][cc0 + tx * 4 + v] = h;
            g_CM_lo[combo][ty * 4 + u][cc0 + tx * 4 + v] = l;
        }
}

// ---- B tile loader: 64 hw rows, ONE plane (hi or lo), 8 cp16/thread ----
static __device__ __forceinline__ void load_B64(
    u32 dst, const __half* X, int hw0, int tid) {
#pragma unroll
    for (int i = 0; i < 8; i++) {
        int f = tid + i * 256;
        int row = f >> 5, c = f & 31;
        cp16(dst + row * ROWB + c * 16, X + (size_t)(hw0 + row) * 256 + c * 8);
    }
}

// ============================================================================
// K2: HMMA reduced projection (fp16 2-term) + relu + pool.
//     grid (15, 4 b, 16 z of 256 hw), block 256 (8 warps = 4m x 2n).
//     Warp tile M32 x N32. 4 steps of 64 hw, double-buffered B (hi only).
// ============================================================================
__global__ void __launch_bounds__(256, 1)
k2_mma() {
    extern __shared__ __align__(16) char sm[];
    u32 smb = smem_u32(sm);

    int tid = threadIdx.x, wid = tid >> 5, lane = tid & 31;
    int src = blockIdx.x / 5, mt = blockIdx.x % 5;
    int b = blockIdx.y, z = blockIdx.z;

    int list[9];
    int n = 0;
    for (int combo = 0; combo < 27; combo++) {
        int e = combo / 3, r = combo % 3;
        int sc = (r == 1) ? e / 3 : e % 3;
        if (sc == src) list[n++] = combo;
    }
    int c0 = list[2 * mt];
    bool has1 = (2 * mt + 1) < 9;
    int c1 = has1 ? list[2 * mt + 1] : c0;

    const __half* XH = g_xT_hi + (size_t)(src * 4 + b) * 4096 * 256;

    // A load: 128 rows (c0: 0-63, c1: 64-127), hi+lo
#pragma unroll
    for (int i = 0; i < 16; i++) {
        int f = tid + i * 256;
        int row = f >> 5, c = f & 31;
        int cb = (row < 64) ? c0 : c1;
        size_t so = ((size_t)cb * 64 + (row & 63)) * 256 + c * 8;
        cp16(smb + SA_HI + row * ROWB + c * 16, &g_CM_hi[0][0][0] + so);
        cp16(smb + SA_LO + row * ROWB + c * 16, &g_CM_lo[0][0][0] + so);
    }
    CP_COMMIT();
    load_B64(smb + SM_B, XH, z * 256, tid);
    CP_COMMIT();

    int mwarp = wid >> 1, nwarp = wid & 1;
    int R0 = mwarp * 32;
    int H = nwarp * 32;

    u32 aoff = (u32)(R0 + (lane & 15)) * ROWB + (lane >> 4) * 16;
    u32 aHi = smb + SA_HI + aoff;
    u32 aLo = smb + SA_LO + aoff;
    u32 boff = (u32)(H + (lane & 7) + ((lane >= 16) ? 8 : 0)) * ROWB + ((lane & 8) ? 16 : 0);

    float psum[2][2] = {}, pmax[2][2] = {};

    for (int step = 0; step < 4; step++) {
        if (step < 3) {
            load_B64(smb + SM_B + ((step + 1) & 1) * BBUF, XH, z * 256 + (step + 1) * 64, tid);
            CP_COMMIT();
            CP_WAIT1();
        } else {
            CP_WAIT0();
        }
        __syncthreads();

        u32 bHi = smb + SM_B + (step & 1) * BBUF + boff;

        float acc[2][4][4] = {};
#pragma unroll
        for (int kk = 0; kk < 16; kk++) {
            u32 kb = kk * 32;
            u32 ah0[4], ah1[4], al0[4], al1[4], bh0[4], bh1[4];
            ldsm4(ah0, aHi + kb);
            ldsm4(ah1, aHi + 16 * ROWB + kb);
            ldsm4(al0, aLo + kb);
            ldsm4(al1, aLo + 16 * ROWB + kb);
            ldsm4(bh0, bHi + kb);
            ldsm4(bh1, bHi + 16 * ROWB + kb);
#pragma unroll
            for (int m = 0; m < 2; m++) {
                const u32* ah = m ? ah1 : ah0;
                const u32* al = m ? al1 : al0;
                mma16816(acc[m][0], ah, bh0);
                mma16816(acc[m][0], al, bh0);
                mma16816(acc[m][1], ah, bh0 + 2);
                mma16816(acc[m][1], al, bh0 + 2);
                mma16816(acc[m][2], ah, bh1);
                mma16816(acc[m][2], al, bh1);
                mma16816(acc[m][3], ah, bh1 + 2);
                mma16816(acc[m][3], al, bh1 + 2);
            }
        }
        // relu + pool (cols are hw)
#pragma unroll
        for (int m = 0; m < 2; m++)
#pragma unroll
            for (int nt = 0; nt < 4; nt++) {
                float r0 = fmaxf(acc[m][nt][0], 0.f), r1 = fmaxf(acc[m][nt][1], 0.f);
                float r2 = fmaxf(acc[m][nt][2], 0.f), r3 = fmaxf(acc[m][nt][3], 0.f);
                psum[m][0] += r0 + r1;
                psum[m][1] += r2 + r3;
                pmax[m][0] = fmaxf(pmax[m][0], fmaxf(r0, r1));
                pmax[m][1] = fmaxf(pmax[m][1], fmaxf(r2, r3));
            }
        __syncthreads();
    }

    // reduce over quad lanes (hw columns within tile)
#pragma unroll
    for (int m = 0; m < 2; m++)
#pragma unroll
        for (int h = 0; h < 2; h++) {
#pragma unroll
            for (int off = 1; off <= 2; off <<= 1) {
                psum[m][h] += __shfl_xor_sync(0xffffffffu, psum[m][h], off);
                pmax[m][h] = fmaxf(pmax[m][h], __shfl_xor_sync(0xffffffffu, pmax[m][h], off));
            }
        }

    float* ps = (float*)(sm + SM_B);        // [128][2]
    float* pm = ps + 256;
    if ((lane & 3) == 0) {
        int g = lane >> 2;
#pragma unroll
        for (int m = 0; m < 2; m++)
#pragma unroll
            for (int h = 0; h < 2; h++) {
                int row = R0 + m * 16 + h * 8 + g;
                ps[row * 2 + nwarp] = psum[m][h];
                pm[row * 2 + nwarp] = pmax[m][h];
            }
    }
    __syncthreads();
    if (tid < 128) {
        float s = ps[tid * 2] + ps[tid * 2 + 1];
        float m = fmaxf(pm[tid * 2], pm[tid * 2 + 1]);
        if (tid < 64 || has1) {
            int cb = (tid < 64) ? c0 : c1;
            g_pp_sum[cb][b][z][tid & 63] = s;
            g_pp_max[cb][b][z][tid & 63] = m;
        }
    }
}

// ============================================================================
// K3: channel-attention math per (e, b). grid (9,4), block 256.
// ============================================================================
__global__ void k3_attn(const float* __restrict__ Wrec) {
    int e = blockIdx.x, b = blockIdx.y;
    __shared__ float fS[64], gS[64], hS[64], vout[64];
    __shared__ float redA[4][64], redB[4][64];
    int tid = threadIdx.x;
    int j = tid & 63, p = tid >> 6;

    if (p < 3) {
        float s = 0.f, m = 0.f;
#pragma unroll
        for (int ch = 0; ch < 16; ch++) {
            s += g_pp_sum[e * 3 + p][b][ch][j];
            m = fmaxf(m, g_pp_max[e * 3 + p][b][ch][j]);
        }
        float val = s * (1.f / 4096.f) + m;
        if (p == 0) gS[j] = val;        // pool(qr)
        else if (p == 1) fS[j] = val;   // pool(kr)
        else hS[j] = val;               // pool(vr)
    }
    __syncthreads();

    float gj = gS[j];
    float lmax = -1e30f;
#pragma unroll
    for (int i = p * 16; i < p * 16 + 16; i++) lmax = fmaxf(lmax, fS[i] * gj);
    redA[p][j] = lmax;
    __syncthreads();
    float mx = fmaxf(fmaxf(redA[0][j], redA[1][j]), fmaxf(redA[2][j], redA[3][j]));
    __syncthreads();
    float den = 0.f, num = 0.f;
#pragma unroll
    for (int i = p * 16; i < p * 16 + 16; i++) {
        float ev = expf(fS[i] * gj - mx);
        den += ev;
        num += hS[i] * ev;
    }
    redA[p][j] = den;
    redB[p][j] = num;
    __syncthreads();
    if (p == 0)
        vout[j] = (redB[0][j] + redB[1][j] + redB[2][j] + redB[3][j]) /
                  (redA[0][j] + redA[1][j] + redA[2][j] + redA[3][j]);
    __syncthreads();

    const float* wr = Wrec + ((size_t)e * 256 + tid) * 64;
    float acc = 0.f;
#pragma unroll 8
    for (int q = 0; q < 64; q++) acc = fmaf(vout[q], wr[q], acc);
    g_o[e][b][tid] = 1.f / (1.f + expf(-acc));
}

// ============================================================================
// K4: build gated split weights g_W5[b][ct][s][hi/lo][128][256]
// ============================================================================
__global__ void k4_w5(const float* __restrict__ Wqkv) {
    int b = blockIdx.x, ct = blockIdx.y, s = blockIdx.z;
    __shared__ float sA[128], sB[128];
    if (threadIdx.x < 128) {
        int c = ct * 128 + threadIdx.x;
        sA[threadIdx.x] = g_o[s][b][c] + g_o[s + 3][b][c] + g_o[s + 6][b][c];
        sB[threadIdx.x] = g_o[3 * s][b][c] + g_o[3 * s + 1][b][c] + g_o[3 * s + 2][b][c];
    }
    __syncthreads();
    const float* Wq = Wqkv + (size_t)(3 * s) * 65536 + (size_t)ct * 128 * 256;
    const float* Wk = Wq + 65536;
    const float* Wv = Wk + 65536;
    size_t base = (((size_t)(b * 2 + ct) * 3 + s) * 2) * 128 * 256;
    for (int i = threadIdx.x; i < 128 * 256; i += 256) {
        int row = i >> 8, cin = i & 255;
        float w = sA[row] * (Wq[row * 256 + cin] + Wv[row * 256 + cin])
                + sB[row] * Wk[row * 256 + cin];
        __half h, l;
        split_h(w, h, l);
        g_W5[base + i] = h;
        g_W5[base + 128 * 256 + i] = l;
    }
}

// ============================================================================
// K5: HMMA output GEMM (fp16 3-term), accumulate 3 sources in registers.
//     grid (2 ct, 4 b, 32 hz of 128 hw), block 256 (4m x 2n warps).
//     Warp tile M32 x N32; 2 steps of 64 hw per s; single B buffer (hi+lo).
// ============================================================================
__global__ void __launch_bounds__(256, 1)
k5_mma(float* __restrict__ out) {
    extern __shared__ __align__(16) char sm[];
    u32 smb = smem_u32(sm);

    int tid = threadIdx.x, wid = tid >> 5, lane = tid & 31;
    int ct = blockIdx.x, b = blockIdx.y, hz = blockIdx.z;

    int mwarp = wid >> 1, nwarp = wid & 1;
    int R0 = mwarp * 32;
    int H = nwarp * 32;

    u32 aoff = (u32)(R0 + (lane & 15)) * ROWB + (lane >> 4) * 16;
    u32 aHi = smb + SA_HI + aoff;
    u32 aLo = smb + SA_LO + aoff;
    u32 boff = (u32)(H + (lane & 7) + ((lane >= 16) ? 8 : 0)) * ROWB + ((lane & 8) ? 16 : 0);

    float acc[2][2][4][4] = {};   // [step][m][n][4]

    for (int s = 0; s < 3; s++) {
        const __half* WA = g_W5 + (((size_t)(b * 2 + ct) * 3 + s) * 2) * 128 * 256;
#pragma unroll
        for (int i = 0; i < 16; i++) {
            int f = tid + i * 256;
            int row = f >> 5, c = f & 31;
            size_t so = (size_t)row * 256 + c * 8;
            cp16(smb + SA_HI + row * ROWB + c * 16, WA + so);
            cp16(smb + SA_LO + row * ROWB + c * 16, WA + 128 * 256 + so);
        }
        CP_COMMIT();

        const __half* XH = g_xT_hi + (size_t)(s * 4 + b) * 4096 * 256;
        const __half* XL = g_xT_lo + (size_t)(s * 4 + b) * 4096 * 256;

#pragma unroll
        for (int step = 0; step < 2; step++) {
            load_B64(smb + SM_B, XH, hz * 128 + step * 64, tid);
            load_B64(smb + SM_B + BBUF, XL, hz * 128 + step * 64, tid);
            CP_COMMIT();
            CP_WAIT0();
            __syncthreads();

            u32 bHi = smb + SM_B + boff;
            u32 bLo = bHi + BBUF;
#pragma unroll
            for (int kk = 0; kk < 16; kk++) {
                u32 kb = kk * 32;
                u32 ah0[4], ah1[4], al0[4], al1[4], bh0[4], bh1[4], bl0[4], bl1[4];
                ldsm4(ah0, aHi + kb);
                ldsm4(ah1, aHi + 16 * ROWB + kb);
                ldsm4(al0, aLo + kb);
                ldsm4(al1, aLo + 16 * ROWB + kb);
                ldsm4(bh0, bHi + kb);
                ldsm4(bh1, bHi + 16 * ROWB + kb);
                ldsm4(bl0, bLo + kb);
                ldsm4(bl1, bLo + 16 * ROWB + kb);
#pragma unroll
                for (int m = 0; m < 2; m++) {
                    const u32* ah = m ? ah1 : ah0;
                    const u32* al = m ? al1 : al0;
                    mma16816(acc[step][m][0], ah, bh0);
                    mma16816(acc[step][m][0], al, bh0);
                    mma16816(acc[step][m][0], ah, bl0);
                    mma16816(acc[step][m][1], ah, bh0 + 2);
                    mma16816(acc[step][m][1], al, bh0 + 2);
                    mma16816(acc[step][m][1], ah, bl0 + 2);
                    mma16816(acc[step][m][2], ah, bh1);
                    mma16816(acc[step][m][2], al, bh1);
                    mma16816(acc[step][m][2], ah, bl1);
                    mma16816(acc[step][m][3], ah, bh1 + 2);
                    mma16816(acc[step][m][3], al, bh1 + 2);
                    mma16816(acc[step][m][3], ah, bl1 + 2);
                }
            }
            __syncthreads();
        }
    }

    // store
    int g = lane >> 2, t = lane & 3;
#pragma unroll
    for (int step = 0; step < 2; step++)
#pragma unroll
        for (int m = 0; m < 2; m++)
#pragma unroll
            for (int nt = 0; nt < 4; nt++) {
                int ch = ct * 128 + R0 + m * 16 + g;
                int col = hz * 128 + step * 64 + H + nt * 8 + 2 * t;
                float2* p0 = (float2*)(out + ((size_t)b * NC + ch) * NHW + col);
                float2* p1 = (float2*)(out + ((size_t)b * NC + ch + 8) * NHW + col);
                *p0 = make_float2(acc[step][m][nt][0], acc[step][m][nt][1]);
                *p1 = make_float2(acc[step][m][nt][2], acc[step][m][nt][3]);
            }
}

// ============================================================================
extern "C" void kernel_launch(void* const* d_in, const int* in_sizes, int n_in,
                              void* d_out, int out_size) {
    (void)in_sizes; (void)n_in; (void)out_size;
    const float* t    = (const float*)d_in[0];
    const float* bb   = (const float*)d_in[1];
    const float* mm   = (const float*)d_in[2];
    const float* Wqkv = (const float*)d_in[3];
    const float* Wred = (const float*)d_in[4];
    const float* Wrec = (const float*)d_in[5];
    float* out = (float*)d_out;

    cudaFuncSetAttribute(k2_mma, cudaFuncAttributeMaxDynamicSharedMemorySize, SMEMSZ);
    cudaFuncSetAttribute(k5_mma, cudaFuncAttributeMaxDynamicSharedMemorySize, SMEMSZ);

    k0_split<<<dim3(12, 8, 16), 256>>>(t, bb, mm);
    k1_cm<<<dim3(27, 4), 256>>>(Wqkv, Wred);
    k2_mma<<<dim3(15, 4, 16), 256, SMEMSZ>>>();
    k3_attn<<<dim3(9, 4), 256>>>(Wrec);
    k4_w5<<<dim3(4, 2, 3), 256>>>(Wqkv);
    k5_mma<<<dim3(2, 4, 32), 256, SMEMSZ>>>(out);
}